// round 1
// baseline (speedup 1.0000x reference)
#include <cuda_runtime.h>
#include <cstdint>

// Problem constants (fixed by the dataset)
#define HCH   512      // channels (d_model)
#define LSEQ  4096     // sequence length
#define BATCH 8
#define TAPS  64       // filter support = D_STATE

// Tiling
#define NT    128              // threads per block
#define RPT   8                // outputs (t positions) per thread
#define TBLK  (NT * RPT)       // 1024 t-positions per block
#define HALO  64
#define UROW  (TBLK + HALO)    // 1088 floats of u per row in smem
#define SKEW(i) ((i) + ((i) >> 5))

typedef unsigned long long ull;

// Precomputed folded filter: K[h,s] = sum_j B[h,j]*C[h,j+s], K[h,0] += D[h]
__device__ float g_K[HCH * TAPS];

__global__ void build_k(const float* __restrict__ B,
                        const float* __restrict__ C,
                        const float* __restrict__ D) {
    int h = blockIdx.x;
    int s = threadIdx.x;            // 0..63
    const float* Bh = B + h * TAPS;
    const float* Ch = C + h * TAPS;
    float acc = (s == 0) ? D[h] : 0.0f;
    #pragma unroll
    for (int j = 0; j < TAPS; ++j) {
        if (j + s < TAPS) acc = fmaf(Bh[j], Ch[j + s], acc);
    }
    g_K[h * TAPS + s] = acc;
}

__device__ __forceinline__ ull pk2(float lo, float hi) {
    ull r;
    asm("mov.b64 %0, {%1, %2};" : "=l"(r) : "f"(lo), "f"(hi));
    return r;
}
__device__ __forceinline__ void fma2(ull& d, ull a, ull b) {
    // d = a * b + d, elementwise on packed f32x2 (Blackwell FFMA2)
    asm("fma.rn.f32x2 %0, %1, %2, %0;" : "+l"(d) : "l"(a), "l"(b));
}

__global__ __launch_bounds__(NT) void conv_k(const float* __restrict__ u,
                                             float* __restrict__ y) {
    __shared__ alignas(16) float sU[2][UROW];            // two batch rows (halo'd)
    __shared__ ull  sC2[TAPS];                            // (c,c) packed coeffs
    __shared__ float sO[2][TBLK + TBLK / 32];             // skewed output staging

    const int tid = threadIdx.x;
    const int t0  = blockIdx.x * TBLK;
    const int h   = blockIdx.y;
    const int b0  = blockIdx.z * 2;                       // batch pair (b0, b0+1)

    const float* u0 = u + ((size_t)b0 * HCH + h) * LSEQ;
    const float* u1 = u0 + (size_t)HCH * LSEQ;

    if (tid < TAPS) {
        float c = g_K[h * TAPS + tid];
        sC2[tid] = pk2(c, c);
    }

    // Fill sU: smem index i <-> global t = t0 - HALO + i  (zeros for t < 0)
    #pragma unroll
    for (int it = 0; it < 3; ++it) {
        int i4 = tid + it * NT;
        if (i4 < UROW / 4) {
            int t = t0 - HALO + i4 * 4;
            float4 v0 = make_float4(0.f, 0.f, 0.f, 0.f);
            float4 v1 = v0;
            if (t >= 0) {
                v0 = *reinterpret_cast<const float4*>(u0 + t);
                v1 = *reinterpret_cast<const float4*>(u1 + t);
            }
            reinterpret_cast<float4*>(sU[0])[i4] = v0;
            reinterpret_cast<float4*>(sU[1])[i4] = v1;
        }
    }
    __syncthreads();

    const int base = HALO + tid * RPT;   // smem idx of this thread's first output t

    ull acc[RPT];
    #pragma unroll
    for (int r = 0; r < RPT; ++r) acc[r] = 0ULL;

    // 16-slot circular register window: slot(d) = d & 15, W[slot] = u pair at idx base+d
    ull W[16];
    {
        const float4* p0 = reinterpret_cast<const float4*>(&sU[0][base - 8]);
        const float4* p1 = reinterpret_cast<const float4*>(&sU[1][base - 8]);
        float4 a0 = p0[0], a1 = p0[1], a2 = p0[2], a3 = p0[3];
        float4 q0 = p1[0], q1 = p1[1], q2 = p1[2], q3 = p1[3];
        W[8]  = pk2(a0.x, q0.x); W[9]  = pk2(a0.y, q0.y);
        W[10] = pk2(a0.z, q0.z); W[11] = pk2(a0.w, q0.w);
        W[12] = pk2(a1.x, q1.x); W[13] = pk2(a1.y, q1.y);
        W[14] = pk2(a1.z, q1.z); W[15] = pk2(a1.w, q1.w);
        W[0]  = pk2(a2.x, q2.x); W[1]  = pk2(a2.y, q2.y);
        W[2]  = pk2(a2.z, q2.z); W[3]  = pk2(a2.w, q2.w);
        W[4]  = pk2(a3.x, q3.x); W[5]  = pk2(a3.y, q3.y);
        W[6]  = pk2(a3.z, q3.z); W[7]  = pk2(a3.w, q3.w);
    }

    #pragma unroll
    for (int c = 0; c < 8; ++c) {
        // Prefetch next 8-window block (d in [-8(c+2), -8(c+2)+7]) into temps
        float4 n0a, n0b, n1a, n1b;
        if (c < 7) {
            int off = base - 8 * (c + 2);        // >= 0, 16B aligned
            n0a = *reinterpret_cast<const float4*>(&sU[0][off]);
            n0b = *reinterpret_cast<const float4*>(&sU[0][off + 4]);
            n1a = *reinterpret_cast<const float4*>(&sU[1][off]);
            n1b = *reinterpret_cast<const float4*>(&sU[1][off + 4]);
        }
        // Taps s = 8c..8c+7 : acc[r] += K[s] * u[base + r - s]
        #pragma unroll
        for (int k = 0; k < 8; ++k) {
            ull c2 = sC2[8 * c + k];             // broadcast LDS.64
            #pragma unroll
            for (int r = 0; r < RPT; ++r)
                fma2(acc[r], c2, W[(r - k - 8 * c) & 15]);
        }
        // Retire old slots, install prefetched block
        if (c < 7) {
            int d0 = -8 * (c + 2);
            W[(d0 + 0) & 15] = pk2(n0a.x, n1a.x);
            W[(d0 + 1) & 15] = pk2(n0a.y, n1a.y);
            W[(d0 + 2) & 15] = pk2(n0a.z, n1a.z);
            W[(d0 + 3) & 15] = pk2(n0a.w, n1a.w);
            W[(d0 + 4) & 15] = pk2(n0b.x, n1b.x);
            W[(d0 + 5) & 15] = pk2(n0b.y, n1b.y);
            W[(d0 + 6) & 15] = pk2(n0b.z, n1b.z);
            W[(d0 + 7) & 15] = pk2(n0b.w, n1b.w);
        }
    }

    // Stage outputs in skewed smem (conflict-free stride-8 STS), then coalesced STG
    #pragma unroll
    for (int r = 0; r < RPT; ++r) {
        float o0, o1;
        asm("mov.b64 {%0, %1}, %2;" : "=f"(o0), "=f"(o1) : "l"(acc[r]));
        int i = tid * RPT + r;
        sO[0][SKEW(i)] = o0;
        sO[1][SKEW(i)] = o1;
    }
    __syncthreads();

    float* y0 = y + ((size_t)b0 * HCH + h) * LSEQ + t0;
    float* y1 = y0 + (size_t)HCH * LSEQ;
    #pragma unroll
    for (int it = 0; it < TBLK / NT; ++it) {
        int i = tid + it * NT;
        y0[i] = sO[0][SKEW(i)];
        y1[i] = sO[1][SKEW(i)];
    }
}

extern "C" void kernel_launch(void* const* d_in, const int* in_sizes, int n_in,
                              void* d_out, int out_size) {
    const float* u = (const float*)d_in[0];   // (8, 512, 4096)
    const float* B = (const float*)d_in[1];   // (512, 64)
    const float* C = (const float*)d_in[2];   // (1, 512, 64)
    const float* D = (const float*)d_in[3];   // (512,)
    float* y = (float*)d_out;                 // (8, 512, 4096)

    build_k<<<HCH, TAPS>>>(B, C, D);

    dim3 grid(LSEQ / TBLK, HCH, BATCH / 2);   // (4, 512, 4)
    conv_k<<<grid, NT>>>(u, y);
}

// round 2
// speedup vs baseline: 1.1739x; 1.1739x over previous
#include <cuda_runtime.h>
#include <cstdint>

// Problem constants (fixed by the dataset)
#define HCH   512
#define LSEQ  4096
#define BATCH 8
#define TAPS  64

// Tiling
#define NT    128
#define RPT   8
#define TBLK  (NT * RPT)          // 1024 outputs per block
#define HALO  64
#define NPAIR (TBLK + HALO)       // 1088 (b0,b1) pairs staged per block
#define OROW  (TBLK + TBLK / 32)  // 1056 floats per skewed output row
#define SKEW(i) ((i) + ((i) >> 5))

typedef unsigned long long ull;

__device__ __forceinline__ ull pk2(float lo, float hi) {
    ull r;
    asm("mov.b64 %0, {%1, %2};" : "=l"(r) : "f"(lo), "f"(hi));
    return r;
}
__device__ __forceinline__ void upk2(ull v, float& lo, float& hi) {
    asm("mov.b64 {%0, %1}, %2;" : "=f"(lo), "=f"(hi) : "l"(v));
}
__device__ __forceinline__ void fma2(ull& d, ull a, ull b) {
    // packed f32x2: d = a*b + d  (FFMA2)
    asm("fma.rn.f32x2 %0, %1, %2, %0;" : "+l"(d) : "l"(a), "l"(b));
}
// swizzle at ull2 (16B) granularity: kills bank conflicts for 64B-stride reads
__device__ __forceinline__ int swz(int i2) { return i2 ^ ((i2 >> 3) & 7); }

__global__ __launch_bounds__(NT) void conv_k(const float* __restrict__ u,
                                             const float* __restrict__ B,
                                             const float* __restrict__ C,
                                             const float* __restrict__ D,
                                             float* __restrict__ y) {
    __shared__ alignas(16) ull sP[NPAIR];   // interleaved (b0,b1) pairs, swizzled
    __shared__ alignas(16) ull sC2[TAPS];   // (c,c) duplicated coefficients

    const int tid = threadIdx.x;
    const int t0  = blockIdx.x * TBLK;
    const int h   = blockIdx.y;
    const int b0  = blockIdx.z * 2;

    const float* u0 = u + ((size_t)b0 * HCH + h) * LSEQ;
    const float* u1 = u0 + (size_t)HCH * LSEQ;

    // ---- Filter: K[h,s] = sum_j B[h,j]*C[h,j+s], K[h,0]+=D[h]  (64 threads) ----
    if (tid < TAPS) {
        const float* Bh = B + h * TAPS;
        const float* Ch = C + h * TAPS;
        float a = (tid == 0) ? D[h] : 0.0f;
        #pragma unroll
        for (int j = 0; j < TAPS; ++j)
            if (j + tid < TAPS) a = fmaf(Bh[j], Ch[j + tid], a);
        sC2[tid] = pk2(a, a);
    }

    // ---- Stage u pairs into swizzled smem: pair index i <-> t = t0 - HALO + i ----
    #pragma unroll
    for (int it = 0; it < 3; ++it) {
        int i4 = tid + it * NT;             // float4-group index
        if (i4 < NPAIR / 4) {
            int t = t0 - HALO + i4 * 4;
            float4 v0 = make_float4(0.f, 0.f, 0.f, 0.f);
            float4 v1 = v0;
            if (t >= 0) {
                v0 = *reinterpret_cast<const float4*>(u0 + t);
                v1 = *reinterpret_cast<const float4*>(u1 + t);
            }
            ulonglong2 w0, w1;
            w0.x = pk2(v0.x, v1.x); w0.y = pk2(v0.y, v1.y);
            w1.x = pk2(v0.z, v1.z); w1.y = pk2(v0.w, v1.w);
            reinterpret_cast<ulonglong2*>(sP)[swz(i4 * 2 + 0)] = w0;
            reinterpret_cast<ulonglong2*>(sP)[swz(i4 * 2 + 1)] = w1;
        }
    }
    __syncthreads();

    const int pbase = HALO + tid * RPT;     // pair index of this thread's output r=0
    const ulonglong2* sPv  = reinterpret_cast<const ulonglong2*>(sP);
    const ulonglong2* sC2v = reinterpret_cast<const ulonglong2*>(sC2);

    #define LD2(p) (sPv[swz((p) >> 1)])    // p must be even

    ull acc[RPT];
    #pragma unroll
    for (int r = 0; r < RPT; ++r) acc[r] = 0ULL;

    // 16-slot circular window: W[d & 15] holds the pair at index pbase + d
    ull W[16];
    {
        ulonglong2 x0 = LD2(pbase - 8), x1 = LD2(pbase - 6),
                   x2 = LD2(pbase - 4), x3 = LD2(pbase - 2);
        ulonglong2 x4 = LD2(pbase + 0), x5 = LD2(pbase + 2),
                   x6 = LD2(pbase + 4), x7 = LD2(pbase + 6);
        W[8]  = x0.x; W[9]  = x0.y; W[10] = x1.x; W[11] = x1.y;
        W[12] = x2.x; W[13] = x2.y; W[14] = x3.x; W[15] = x3.y;
        W[0]  = x4.x; W[1]  = x4.y; W[2]  = x5.x; W[3]  = x5.y;
        W[4]  = x6.x; W[5]  = x6.y; W[6]  = x7.x; W[7]  = x7.y;
    }

    #pragma unroll
    for (int c = 0; c < 8; ++c) {
        const int d0 = -8 * (c + 2);        // refill block for chunk c+1
        const int s  = d0 & 15;             // 0 or 8, compile-time

        // taps k = 0..3
        {
            ulonglong2 q0 = sC2v[4 * c + 0];   // k=0,1 (broadcast LDS.128)
            ulonglong2 q1 = sC2v[4 * c + 1];   // k=2,3
            #pragma unroll
            for (int r = 0; r < RPT; ++r) fma2(acc[r], q0.x, W[(r - 0 - 8 * c) & 15]);
            #pragma unroll
            for (int r = 0; r < RPT; ++r) fma2(acc[r], q0.y, W[(r - 1 - 8 * c) & 15]);
            #pragma unroll
            for (int r = 0; r < RPT; ++r) fma2(acc[r], q1.x, W[(r - 2 - 8 * c) & 15]);
            #pragma unroll
            for (int r = 0; r < RPT; ++r) fma2(acc[r], q1.y, W[(r - 3 - 8 * c) & 15]);
        }
        // slots s+4..s+7 are dead after k=3 -> refill them now (direct into W)
        if (c < 7) {
            ulonglong2 a = LD2(pbase + d0 + 4);
            ulonglong2 b = LD2(pbase + d0 + 6);
            W[s + 4] = a.x; W[s + 5] = a.y; W[s + 6] = b.x; W[s + 7] = b.y;
        }
        // taps k = 4..7
        {
            ulonglong2 q2 = sC2v[4 * c + 2];   // k=4,5
            ulonglong2 q3 = sC2v[4 * c + 3];   // k=6,7
            #pragma unroll
            for (int r = 0; r < RPT; ++r) fma2(acc[r], q2.x, W[(r - 4 - 8 * c) & 15]);
            #pragma unroll
            for (int r = 0; r < RPT; ++r) fma2(acc[r], q2.y, W[(r - 5 - 8 * c) & 15]);
            #pragma unroll
            for (int r = 0; r < RPT; ++r) fma2(acc[r], q3.x, W[(r - 6 - 8 * c) & 15]);
            #pragma unroll
            for (int r = 0; r < RPT; ++r) fma2(acc[r], q3.y, W[(r - 7 - 8 * c) & 15]);
        }
        // slots s..s+3 dead after k=7 -> refill
        if (c < 7) {
            ulonglong2 a = LD2(pbase + d0 + 0);
            ulonglong2 b = LD2(pbase + d0 + 2);
            W[s + 0] = a.x; W[s + 1] = a.y; W[s + 2] = b.x; W[s + 3] = b.y;
        }
    }
    #undef LD2

    // ---- Output: stage in skewed smem (reusing sP), then coalesced STG ----
    __syncthreads();                         // all sP/sC2 reads done block-wide
    float* sO = reinterpret_cast<float*>(sP);
    #pragma unroll
    for (int r = 0; r < RPT; ++r) {
        float o0, o1;
        upk2(acc[r], o0, o1);
        int i = tid * RPT + r;
        sO[SKEW(i)]        = o0;
        sO[OROW + SKEW(i)] = o1;
    }
    __syncthreads();

    float* y0 = y + ((size_t)b0 * HCH + h) * LSEQ + t0;
    float* y1 = y0 + (size_t)HCH * LSEQ;
    #pragma unroll
    for (int it = 0; it < RPT; ++it) {
        int i = tid + it * NT;
        y0[i] = sO[SKEW(i)];
        y1[i] = sO[OROW + SKEW(i)];
    }
}

extern "C" void kernel_launch(void* const* d_in, const int* in_sizes, int n_in,
                              void* d_out, int out_size) {
    const float* u = (const float*)d_in[0];   // (8, 512, 4096)
    const float* B = (const float*)d_in[1];   // (512, 64)
    const float* C = (const float*)d_in[2];   // (1, 512, 64)
    const float* D = (const float*)d_in[3];   // (512,)
    float* y = (float*)d_out;                 // (8, 512, 4096)

    dim3 grid(LSEQ / TBLK, HCH, BATCH / 2);   // (4, 512, 4) = 8192 blocks
    conv_k<<<grid, NT>>>(u, B, C, D, y);
}

// round 3
// speedup vs baseline: 1.1963x; 1.0191x over previous
#include <cuda_runtime.h>
#include <cstdint>

// Problem constants (fixed by the dataset)
#define HCH   512
#define LSEQ  4096
#define BATCH 8
#define TAPS  64

// Tiling
#define NT    128
#define RPT   16
#define TBLK  (NT * RPT)          // 2048 outputs per block
#define HALO  64
#define NPAIR (TBLK + HALO)       // 2112 (b0,b1) pairs staged per block
#define OROW  (TBLK + TBLK / 32)  // 2112 floats per skewed output row
#define SKEW(i) ((i) + ((i) >> 5))
#define WSZ   24
#define SLOT(d) ((((d) % WSZ) + WSZ) % WSZ)

typedef unsigned long long ull;

__device__ __forceinline__ ull pk2(float lo, float hi) {
    ull r;
    asm("mov.b64 %0, {%1, %2};" : "=l"(r) : "f"(lo), "f"(hi));
    return r;
}
__device__ __forceinline__ void upk2(ull v, float& lo, float& hi) {
    asm("mov.b64 {%0, %1}, %2;" : "=f"(lo), "=f"(hi) : "l"(v));
}
__device__ __forceinline__ void fma2(ull& d, ull a, ull b) {
    asm("fma.rn.f32x2 %0, %1, %2, %0;" : "+l"(d) : "l"(a), "l"(b));
}
// swizzle at ull2 (16B) granularity: spreads 128B-stride accesses over all banks
__device__ __forceinline__ int swz(int i2) { return i2 ^ ((i2 >> 3) & 7); }

__global__ __launch_bounds__(NT) void conv_k(const float* __restrict__ u,
                                             const float* __restrict__ B,
                                             const float* __restrict__ C,
                                             const float* __restrict__ D,
                                             float* __restrict__ y) {
    __shared__ alignas(16) ull sP[NPAIR];   // interleaved (b0,b1) pairs, swizzled
    __shared__ alignas(16) ull sC2[TAPS];   // (c,c) duplicated coefficients

    const int tid = threadIdx.x;
    const int t0  = blockIdx.x * TBLK;
    const int h   = blockIdx.y;
    const int b0  = blockIdx.z * 2;

    const float* u0 = u + ((size_t)b0 * HCH + h) * LSEQ;
    const float* u1 = u0 + (size_t)HCH * LSEQ;

    // ---- Filter: K[h,s] = sum_j B[h,j]*C[h,j+s], K[h,0]+=D[h] ----
    if (tid < TAPS) {
        const float* Bh = B + h * TAPS;
        const float* Ch = C + h * TAPS;
        float a = (tid == 0) ? D[h] : 0.0f;
        #pragma unroll
        for (int j = 0; j < TAPS; ++j)
            if (j + tid < TAPS) a = fmaf(Bh[j], Ch[j + tid], a);
        sC2[tid] = pk2(a, a);
    }

    // ---- Stage u pairs into swizzled smem: pair index i <-> t = t0 - HALO + i ----
    #pragma unroll
    for (int it = 0; it < 5; ++it) {
        int i4 = tid + it * NT;             // float4-group index, < NPAIR/4 = 528
        if (i4 < NPAIR / 4) {
            int t = t0 - HALO + i4 * 4;
            float4 v0 = make_float4(0.f, 0.f, 0.f, 0.f);
            float4 v1 = v0;
            if (t >= 0) {
                v0 = *reinterpret_cast<const float4*>(u0 + t);
                v1 = *reinterpret_cast<const float4*>(u1 + t);
            }
            ulonglong2 w0, w1;
            w0.x = pk2(v0.x, v1.x); w0.y = pk2(v0.y, v1.y);
            w1.x = pk2(v0.z, v1.z); w1.y = pk2(v0.w, v1.w);
            reinterpret_cast<ulonglong2*>(sP)[swz(i4 * 2 + 0)] = w0;
            reinterpret_cast<ulonglong2*>(sP)[swz(i4 * 2 + 1)] = w1;
        }
    }
    __syncthreads();

    const int pbase = HALO + tid * RPT;     // pair index of this thread's output r=0
    const ulonglong2* sPv  = reinterpret_cast<const ulonglong2*>(sP);
    const ulonglong2* sC2v = reinterpret_cast<const ulonglong2*>(sC2);

    #define LD2(p) (sPv[swz((p) >> 1)])    // p must be even

    ull acc[RPT];
    #pragma unroll
    for (int r = 0; r < RPT; ++r) acc[r] = 0ULL;

    // 24-slot circular window: W[SLOT(d)] holds the pair at index pbase + d
    ull W[WSZ];
    #pragma unroll
    for (int m = 0; m < 12; ++m) {
        int d = -8 + 2 * m;                 // covers d in [-8, 15]
        ulonglong2 x = LD2(pbase + d);
        W[SLOT(d)] = x.x;
        W[SLOT(d + 1)] = x.y;
    }

    // coefficient pair for taps (0,1) of chunk 0
    ulonglong2 cq01 = sC2v[0];

    #pragma unroll
    for (int c = 0; c < 8; ++c) {
        const int d0 = -8 * (c + 2);        // refill block base (even)

        #define TAP(k_, q_)                                              \
            { _Pragma("unroll")                                          \
              for (int r = 0; r < RPT; ++r)                              \
                  fma2(acc[r], (q_), W[SLOT(r - (k_) - 8 * c)]); }
        #define RF(j_)                                                   \
            { ulonglong2 x = LD2(pbase + d0 + (j_));                     \
              W[SLOT(d0 + (j_))]     = x.x;                              \
              W[SLOT(d0 + (j_) + 1)] = x.y; }

        ulonglong2 cq23 = sC2v[4 * c + 1];
        TAP(0, cq01.x)
        TAP(1, cq01.y)
        ulonglong2 cq45 = sC2v[4 * c + 2];
        if (c < 7) RF(6)                     // slots of old (14-8c,15-8c): dead after tap 1
        TAP(2, cq23.x)
        TAP(3, cq23.y)
        ulonglong2 cq67 = sC2v[4 * c + 3];
        if (c < 7) RF(4)                     // dead after tap 3
        TAP(4, cq45.x)
        TAP(5, cq45.y)
        if (c < 7) cq01 = sC2v[4 * (c + 1)]; // prefetch next chunk taps (0,1)
        if (c < 7) RF(2)                     // dead after tap 5
        TAP(6, cq67.x)
        TAP(7, cq67.y)
        if (c < 7) RF(0)                     // dead after tap 7

        #undef TAP
        #undef RF
    }
    #undef LD2

    // ---- Output: stage in skewed smem (reusing sP), then coalesced STG ----
    __syncthreads();                         // all sP/sC2 reads done block-wide
    float* sO = reinterpret_cast<float*>(sP);
    #pragma unroll
    for (int r = 0; r < RPT; ++r) {
        float o0, o1;
        upk2(acc[r], o0, o1);
        int i = tid * RPT + r;
        sO[SKEW(i)]        = o0;
        sO[OROW + SKEW(i)] = o1;
    }
    __syncthreads();

    float* y0 = y + ((size_t)b0 * HCH + h) * LSEQ + t0;
    float* y1 = y0 + (size_t)HCH * LSEQ;
    #pragma unroll
    for (int it = 0; it < RPT; ++it) {
        int i = tid + it * NT;
        y0[i] = sO[SKEW(i)];
        y1[i] = sO[OROW + SKEW(i)];
    }
}

extern "C" void kernel_launch(void* const* d_in, const int* in_sizes, int n_in,
                              void* d_out, int out_size) {
    const float* u = (const float*)d_in[0];   // (8, 512, 4096)
    const float* B = (const float*)d_in[1];   // (512, 64)
    const float* C = (const float*)d_in[2];   // (1, 512, 64)
    const float* D = (const float*)d_in[3];   // (512,)
    float* y = (float*)d_out;                 // (8, 512, 4096)

    dim3 grid(LSEQ / TBLK, HCH, BATCH / 2);   // (2, 512, 4) = 4096 blocks
    conv_k<<<grid, NT>>>(u, B, C, D, y);
}

// round 5
// speedup vs baseline: 1.3894x; 1.1614x over previous
#include <cuda_runtime.h>
#include <cuda_bf16.h>
#include <cstdint>

#define HCH  512
#define LSEQ 4096
#define NB   8
#define TAPS 64

#define NT    256              // 8 warps
#define NWARP 8
#define NCOL  16               // columns per CTA: 2 seq-tiles x 8 batches
#define TCTA  256              // t-positions per CTA (2 tiles of 128)
#define BSTR  100              // uint32 words per B column (96 used + 4 pad) -> conflict-free
#define OSTR  132              // floats per output staging row (16B-aligned, conflict-free)

__device__ __forceinline__ uint32_t pk_bf2f(float a, float b) {
    __nv_bfloat162 t = __floats2bfloat162_rn(a, b);   // .x = a (low), .y = b (high)
    return *reinterpret_cast<uint32_t*>(&t);
}

__device__ __forceinline__ void mma_bf16(float* d, const uint32_t* a,
                                         uint32_t b0, uint32_t b1) {
    asm volatile(
        "mma.sync.aligned.m16n8k16.row.col.f32.bf16.bf16.f32 "
        "{%0,%1,%2,%3}, {%4,%5,%6,%7}, {%8,%9}, {%0,%1,%2,%3};"
        : "+f"(d[0]), "+f"(d[1]), "+f"(d[2]), "+f"(d[3])
        : "r"(a[0]), "r"(a[1]), "r"(a[2]), "r"(a[3]), "r"(b0), "r"(b1));
}

__global__ __launch_bounds__(NT) void conv_mma(const float* __restrict__ up,
                                               const float* __restrict__ Bp,
                                               const float* __restrict__ Cp,
                                               const float* __restrict__ Dp,
                                               float* __restrict__ yp) {
    __shared__ float    sK[TAPS];
    __shared__ uint32_t sBh[NCOL * BSTR];     // bf16-pair words, hi split
    __shared__ uint32_t sBl[NCOL * BSTR];     // lo split
    __shared__ float    sO[NCOL * OSTR];      // output staging

    const int tid  = threadIdx.x;
    const int wid  = tid >> 5;
    const int lane = tid & 31;
    const int h    = blockIdx.y;
    const int t0   = blockIdx.x * TCTA;

    const float* uh = up + (size_t)h * LSEQ;
    float*       yh = yp + (size_t)h * LSEQ;

    // ---- B im2col: per column n=(tile,b), window u[tbase-64 .. tbase+127] ----
    // word w of column n covers e = 4*(w>>1) + 2*(w&1) + {0,1}
    #pragma unroll
    for (int it = 0; it < 3; ++it) {
        int idx = tid + it * NT;               // < NCOL*48 = 768
        int n = idx / 48, q = idx - n * 48;    // q: float4-group within window
        int tile = n >> 3, b = n & 7;
        int t = t0 + tile * 128 - 64 + q * 4;
        float4 v = make_float4(0.f, 0.f, 0.f, 0.f);
        if (t >= 0)
            v = *reinterpret_cast<const float4*>(uh + (size_t)b * (HCH * (size_t)LSEQ) + t);
        uint32_t h0 = pk_bf2f(v.x, v.y), h1 = pk_bf2f(v.z, v.w);
        __nv_bfloat162 bh0 = *reinterpret_cast<__nv_bfloat162*>(&h0);
        __nv_bfloat162 bh1 = *reinterpret_cast<__nv_bfloat162*>(&h1);
        uint32_t l0 = pk_bf2f(v.x - __bfloat162float(bh0.x), v.y - __bfloat162float(bh0.y));
        uint32_t l1 = pk_bf2f(v.z - __bfloat162float(bh1.x), v.w - __bfloat162float(bh1.y));
        sBh[n * BSTR + q * 2]     = h0;
        sBh[n * BSTR + q * 2 + 1] = h1;
        sBl[n * BSTR + q * 2]     = l0;
        sBl[n * BSTR + q * 2 + 1] = l1;
    }

    // ---- K[h,s] = sum_j B[h,j]*C[h,j+s], K[h,0] += D[h] ----
    if (tid < TAPS) {
        const float* Bh_ = Bp + h * TAPS;
        const float* Ch_ = Cp + h * TAPS;
        float a = (tid == 0) ? Dp[h] : 0.0f;
        #pragma unroll
        for (int j = 0; j < TAPS; ++j)
            if (j + tid < TAPS) a = fmaf(Bh_[j], Ch_[j + tid], a);
        sK[tid] = a;
    }
    __syncthreads();

    // ---- Build A fragments: A[m,k] = K[64 + m - k - 16d], d = 0..4 ----
    // frag a0:(r,c0/c0+1) a1:(r+8,..) a2:(r,c0+8..) a3 == a0 pattern shifted
    uint32_t ah[5][4], al[5][4];
    {
        const int r  = lane >> 2;
        const int c0 = (lane & 3) * 2;
        #pragma unroll
        for (int d = 0; d < 5; ++d) {
            int s0 = 64 - 16 * d + r - c0;
            float f[6];                        // s0+8, s0+7, s0, s0-1, s0-8, s0-9
            #pragma unroll
            for (int q = 0; q < 6; ++q) {
                int s = s0 + 8 - q - ((q >= 2) ? (q - 2) / 2 * 6 : 0); // not used; explicit below
                f[q] = 0.f;
            }
            int ss[6] = { s0 + 8, s0 + 7, s0, s0 - 1, s0 - 8, s0 - 9 };
            #pragma unroll
            for (int q = 0; q < 6; ++q)
                f[q] = (ss[q] >= 0 && ss[q] < TAPS) ? sK[ss[q]] : 0.0f;
            uint32_t w0 = pk_bf2f(f[2], f[3]);   // a0: (r,c0),(r,c0+1)
            uint32_t w1 = pk_bf2f(f[0], f[1]);   // a1: (r+8,...)
            uint32_t w2 = pk_bf2f(f[4], f[5]);   // a2: (r, c0+8...)
            __nv_bfloat162 x0 = *reinterpret_cast<__nv_bfloat162*>(&w0);
            __nv_bfloat162 x1 = *reinterpret_cast<__nv_bfloat162*>(&w1);
            __nv_bfloat162 x2 = *reinterpret_cast<__nv_bfloat162*>(&w2);
            ah[d][0] = w0; ah[d][1] = w1; ah[d][2] = w2; ah[d][3] = w0;
            al[d][0] = pk_bf2f(f[2] - __bfloat162float(x0.x), f[3] - __bfloat162float(x0.y));
            al[d][1] = pk_bf2f(f[0] - __bfloat162float(x1.x), f[1] - __bfloat162float(x1.y));
            al[d][2] = pk_bf2f(f[4] - __bfloat162float(x2.x), f[5] - __bfloat162float(x2.y));
            al[d][3] = al[d][0];
        }
    }

    // ---- Banded GEMM: warp wid -> row block jb, two n8 groups ----
    const int jb = wid;
    float acc0[4] = {0.f, 0.f, 0.f, 0.f};
    float acc1[4] = {0.f, 0.f, 0.f, 0.f};
    {
        const int n0 = lane >> 2;              // ng=0 column
        const int wq = lane & 3;
        #pragma unroll
        for (int d = 0; d < 5; ++d) {
            const int kb = jb + d;
            const int w  = kb * 8 + wq;
            uint32_t b0h = sBh[n0 * BSTR + w], b1h = sBh[n0 * BSTR + w + 4];
            uint32_t b0l = sBl[n0 * BSTR + w], b1l = sBl[n0 * BSTR + w + 4];
            mma_bf16(acc0, ah[d], b0h, b1h);
            mma_bf16(acc0, ah[d], b0l, b1l);
            mma_bf16(acc0, al[d], b0h, b1h);
            uint32_t c0h = sBh[(n0 + 8) * BSTR + w], c1h = sBh[(n0 + 8) * BSTR + w + 4];
            uint32_t c0l = sBl[(n0 + 8) * BSTR + w], c1l = sBl[(n0 + 8) * BSTR + w + 4];
            mma_bf16(acc1, ah[d], c0h, c1h);
            mma_bf16(acc1, ah[d], c0l, c1l);
            mma_bf16(acc1, al[d], c0h, c1h);
        }
    }

    // ---- Stage D fragments to smem (conflict-free), then coalesced STG ----
    {
        const int j = jb * 16 + (lane >> 2);
        const int n = (lane & 3) * 2;
        sO[n * OSTR + j]           = acc0[0];
        sO[(n + 1) * OSTR + j]     = acc0[1];
        sO[n * OSTR + j + 8]       = acc0[2];
        sO[(n + 1) * OSTR + j + 8] = acc0[3];
        sO[(n + 8) * OSTR + j]           = acc1[0];
        sO[(n + 9) * OSTR + j]     = acc1[1];
        sO[(n + 8) * OSTR + j + 8]       = acc1[2];
        sO[(n + 9) * OSTR + j + 8] = acc1[3];
    }
    __syncthreads();

    #pragma unroll
    for (int it = 0; it < 2; ++it) {
        int idx = tid + it * NT;               // < NCOL*32 = 512
        int n = idx >> 5, g = idx & 31;
        float4 v = *reinterpret_cast<float4*>(&sO[n * OSTR + g * 4]);
        int tile = n >> 3, b = n & 7;
        *reinterpret_cast<float4*>(
            yh + (size_t)b * (HCH * (size_t)LSEQ) + t0 + tile * 128 + g * 4) = v;
    }
}

extern "C" void kernel_launch(void* const* d_in, const int* in_sizes, int n_in,
                              void* d_out, int out_size) {
    const float* u = (const float*)d_in[0];   // (8, 512, 4096)
    const float* B = (const float*)d_in[1];   // (512, 64)
    const float* C = (const float*)d_in[2];   // (1, 512, 64)
    const float* D = (const float*)d_in[3];   // (512,)
    float* y = (float*)d_out;                 // (8, 512, 4096)

    dim3 grid(LSEQ / TCTA, HCH);              // (16, 512) = 8192 CTAs
    conv_mma<<<grid, NT>>>(u, B, C, D, y);
}